// round 13
// baseline (speedup 1.0000x reference)
#include <cuda_runtime.h>
#include <cuda_fp16.h>
#include <cstdint>

#define TPB    128
#define HD     64
#define STEPS  8

// SW128 swizzle (Swizzle<3,4,3>): XOR bits[6:4] with bits[9:7]
#define SWZ(o) ((o) ^ (((o) >> 3) & 0x70u))

// ---------------- SMEM layout (bytes) ----------------
#define OFF_WT    0        // W_tau fp16 [64 n][64 k] swz (128B rows)  = 8192
#define OFF_WH    8192     // W_h                                        8192
#define OFF_UBT   16384    // U_tau|b_tau fp16 [64 n][16 k] (32B rows) = 2048
#define OFF_UBH   18432    // U_h|b_h                                    2048
#define OFF_WO    20480    // W_out 3x64 f32 = 768, pad 1024
#define OFF_COORD 21504    // 128 x float4                               2048
#define OFF_ST    23552    // state fp32 float2 x 4096 slots           = 32768
#define SMEM_BYTES 56320   // x4 blocks = 225 KB < 228 KB/SM

__device__ __forceinline__ uint32_t smem_u32(const void* p) {
    uint32_t a;
    asm("{ .reg .u64 tmp; cvta.to.shared.u64 tmp, %1; cvt.u32.u64 %0, tmp; }"
        : "=r"(a) : "l"(p));
    return a;
}

// fp16 mma.sync (sm_80 baseline ISA, legal on compute_103)
#define MMA(D, A, B0, B1)                                                        \
    asm volatile("mma.sync.aligned.m16n8k16.row.col.f32.f16.f16.f32 "            \
        "{%0,%1,%2,%3}, {%4,%5,%6,%7}, {%8,%9}, {%0,%1,%2,%3};"                  \
        : "+f"((D)[0]), "+f"((D)[1]), "+f"((D)[2]), "+f"((D)[3])                 \
        : "r"((A)[0]), "r"((A)[1]), "r"((A)[2]), "r"((A)[3]),                    \
          "r"(B0), "r"(B1))

#define LDSM_X4(R, addr)                                                         \
    asm volatile("ldmatrix.sync.aligned.m8n8.x4.shared.b16 {%0,%1,%2,%3}, [%4];" \
        : "=r"((R)[0]), "=r"((R)[1]), "=r"((R)[2]), "=r"((R)[3])                 \
        : "r"(addr))

#define LDSM_X2(R, addr)                                                         \
    asm volatile("ldmatrix.sync.aligned.m8n8.x2.shared.b16 {%0,%1}, [%2];"       \
        : "=r"((R)[0]), "=r"((R)[1]) : "r"(addr))

#define TANHF(r, x) asm("tanh.approx.f32 %0, %1;" : "=f"(r) : "f"(x))

// liquid-ODE pointwise update (tau math as verified; sigmoid via tanh.approx)
__device__ __forceinline__ float liq(float ta, float fa, float hold)
{
    ta = fminf(fmaxf(ta, -50.0f), 50.0f);
    const float sp   = __logf(1.0f + __expf(ta));
    const float tau  = fmaf(sp, 9.9f, 0.1f);
    float th;  TANHF(th, 0.5f * fa);
    const float fs   = fmaf(0.5f, th, 0.5f);
    const float dh   = fmaf(-hold, __fdividef(1.0f, tau), fs);
    return fmaf(0.125f, dh, hold);
}

// epilogue for one (row, col-pair). State slot is plain fp32 float2
// (lane-private). Returns packed fp16 pair = next step's A-fragment half.
__device__ __forceinline__ uint32_t epi2(
    float ta0, float ta1, float fa0, float fa1,
    char* smem, uint32_t soff)
{
    const float2 hold = *reinterpret_cast<const float2*>(smem + soff);
    const float h0n = liq(ta0, fa0, hold.x);
    const float h1n = liq(ta1, fa1, hold.y);
    *reinterpret_cast<float2*>(smem + soff) = make_float2(h0n, h1n);
    __half2 hp = __floats2half2_rn(h0n, h1n);
    return *reinterpret_cast<uint32_t*>(&hp);
}

// one recurrence step: MMAs read acur, epilogues write anx (+ state SMEM).
// p2=1 B address = boff ^ 64: pre-swizzle bit 6 is 0 (bcol<=48), so setting
// it cannot carry, and SWZ's mask (from bits [9:7]) is unchanged -> XOR exact.
__device__ __forceinline__ void do_step(
    char* smem,
    const uint32_t (&acur)[2][4][4], uint32_t (&anx)[2][4][4],
    const uint32_t (&acoord)[2][4],
    const uint32_t (&boffT)[8],
    uint32_t ubbT, uint32_t stb)
{
    #pragma unroll
    for (int nt = 0; nt < 8; nt++) {
        float dt0[4] = {0,0,0,0}, dt1[4] = {0,0,0,0};
        float df0[4] = {0,0,0,0}, df1[4] = {0,0,0,0};

        #pragma unroll
        for (int p2 = 0; p2 < 2; p2++) {
            const uint32_t ba = p2 ? (boffT[nt] ^ 64u) : boffT[nt];
            uint32_t bt[4], bh[4];
            LDSM_X4(bt, ba);
            LDSM_X4(bh, ba + 8192u);   // W_h mirrors W_tau layout (bank offset)
            #pragma unroll
            for (int q = 0; q < 2; q++) {
                const int kk = 2*p2 + q;
                MMA(dt0, acur[0][kk], bt[2*q], bt[2*q+1]);
                MMA(dt1, acur[1][kk], bt[2*q], bt[2*q+1]);
                MMA(df0, acur[0][kk], bh[2*q], bh[2*q+1]);
                MMA(df1, acur[1][kk], bh[2*q], bh[2*q+1]);
            }
        }
        // augmented-K chunk: A = (cx,cy,cz,1,0...), B = (U|b|0...) rows
        {
            uint32_t ubt[2], ubh[2];
            LDSM_X2(ubt, ubbT + (uint32_t)(nt*256));
            LDSM_X2(ubh, ubbT + (uint32_t)(nt*256) + 2048u);
            MMA(dt0, acoord[0], ubt[0], ubt[1]);
            MMA(dt1, acoord[1], ubt[0], ubt[1]);
            MMA(df0, acoord[0], ubh[0], ubh[1]);
            MMA(df1, acoord[1], ubh[0], ubh[1]);
        }

        // epilogues: lane-private fp32 state; outputs ARE next A fragments
        const uint32_t sbase = stb + (uint32_t)(nt*4096);
        anx[0][nt>>1][(nt&1)*2 + 0] = epi2(dt0[0], dt0[1], df0[0], df0[1], smem, sbase + 0);
        anx[0][nt>>1][(nt&1)*2 + 1] = epi2(dt0[2], dt0[3], df0[2], df0[3], smem, sbase + 256);
        anx[1][nt>>1][(nt&1)*2 + 0] = epi2(dt1[0], dt1[1], df1[0], df1[1], smem, sbase + 512);
        anx[1][nt>>1][(nt&1)*2 + 1] = epi2(dt1[2], dt1[3], df1[2], df1[3], smem, sbase + 768);
    }
}

__global__ void __launch_bounds__(TPB, 4) liquid_ode_mma_kernel(
    const float* __restrict__ coords,
    const float* __restrict__ W_h,
    const float* __restrict__ U_h,
    const float* __restrict__ b_h,
    const float* __restrict__ W_tau,
    const float* __restrict__ U_tau,
    const float* __restrict__ b_tau,
    const float* __restrict__ W_out,
    const float* __restrict__ b_out,
    float* __restrict__ out,
    int N)
{
    extern __shared__ char smem[];
    const uint32_t sb = smem_u32(smem);
    const int t    = threadIdx.x;
    const int lane = t & 31;
    const int wid  = t >> 5;
    const int gq   = lane >> 2;
    const int tig  = lane & 3;
    const int warpM = wid * 32;

    // ---- prologue ----
    for (int idx = t; idx < HD * HD; idx += TPB) {
        const int n = idx >> 6, k = idx & 63;
        const uint32_t sw = SWZ((uint32_t)(n * 128 + k * 2));
        *reinterpret_cast<__half*>(smem + OFF_WT + sw) = __float2half_rn(W_tau[idx]);
        *reinterpret_cast<__half*>(smem + OFF_WH + sw) = __float2half_rn(W_h[idx]);
    }
    for (int idx = t; idx < HD * 16; idx += TPB) {
        const int n = idx >> 4, k = idx & 15;
        float vt = 0.f, vh = 0.f;
        if (k < 3)       { vt = U_tau[n*3 + k]; vh = U_h[n*3 + k]; }
        else if (k == 3) { vt = b_tau[n];       vh = b_h[n]; }
        *reinterpret_cast<__half*>(smem + OFF_UBT + idx*2) = __float2half_rn(vt);
        *reinterpret_cast<__half*>(smem + OFF_UBH + idx*2) = __float2half_rn(vh);
    }
    {
        const int p = blockIdx.x * TPB + t;
        reinterpret_cast<float4*>(smem + OFF_COORD)[t] =
            make_float4(coords[3*p], coords[3*p+1], coords[3*p+2], 0.f);
        float* sWo = reinterpret_cast<float*>(smem + OFF_WO);
        for (int i = t; i < 192; i += TPB) sWo[i] = W_out[i];
        float2* s2 = reinterpret_cast<float2*>(smem + OFF_ST);
        for (int i = t; i < 4096; i += TPB) s2[i] = make_float2(0.f, 0.f);   // h = 0
    }
    __syncthreads();

    // constant A-fragment regs for the augmented-K chunk: cols (cx,cy,cz,1,0..)
    uint32_t acoord[2][4];
    {
        const float4* sc = reinterpret_cast<const float4*>(smem + OFF_COORD);
        #pragma unroll
        for (int m = 0; m < 2; m++) {
            const float4 c0 = sc[warpM + m*16 + gq];
            const float4 c1 = sc[warpM + m*16 + gq + 8];
            uint32_t p0 = 0u, p1 = 0u;
            if (tig == 0) {
                __half2 h0 = __floats2half2_rn(c0.x, c0.y);
                __half2 h1 = __floats2half2_rn(c1.x, c1.y);
                p0 = *reinterpret_cast<uint32_t*>(&h0);
                p1 = *reinterpret_cast<uint32_t*>(&h1);
            } else if (tig == 1) {
                __half2 h0 = __floats2half2_rn(c0.z, 1.0f);
                __half2 h1 = __floats2half2_rn(c1.z, 1.0f);
                p0 = *reinterpret_cast<uint32_t*>(&h0);
                p1 = *reinterpret_cast<uint32_t*>(&h1);
            }
            acoord[m][0] = p0;
            acoord[m][1] = p1;
            acoord[m][2] = 0u;
            acoord[m][3] = 0u;
        }
    }

    // precomputed ldmatrix base addresses (p2=0; p2=1 via ^64, SWZ-exact)
    uint32_t boffT[8];
    {
        const uint32_t brow = (uint32_t)(lane & 7);
        const uint32_t bcol = ((lane & 16) ? 32u : 0u) + ((lane & 8) ? 16u : 0u);
        #pragma unroll
        for (int nt = 0; nt < 8; nt++)
            boffT[nt] = sb + OFF_WT +
                SWZ((uint32_t)((nt*8 + brow) * 128) + bcol);
    }
    const uint32_t ubbT = sb + OFF_UBT + (uint32_t)((lane & 7) * 32)
                        + ((lane & 8) ? 16u : 0u);
    const uint32_t stb  = (uint32_t)(OFF_ST + wid*1024 + lane*8);

    // A double buffer (h fp16), register-resident; h0 = 0
    uint32_t a0[2][4][4], a1[2][4][4];
    #pragma unroll
    for (int m = 0; m < 2; m++)
        #pragma unroll
        for (int kk = 0; kk < 4; kk++)
            #pragma unroll
            for (int j = 0; j < 4; j++) { a0[m][kk][j] = 0u; a1[m][kk][j] = 0u; }

    // ---- 8 steps, sync-free, ping-pong A buffers (no copy) ----
    #pragma unroll 1
    for (int s = 0; s < STEPS / 2; s++) {
        do_step(smem, a0, a1, acoord, boffT, ubbT, stb);
        do_step(smem, a1, a0, acoord, boffT, ubbT, stb);
    }

    __syncwarp();   // state rows are warp-private; cross-lane writes -> readout

    // ---- readout: thread t reads its own row t from fp32 state ----
    {
        const float* sWo = reinterpret_cast<const float*>(smem + OFF_WO);
        float v0 = 0.f, v1 = 0.f, v2 = 0.f;
        #pragma unroll
        for (int gp = 0; gp < 32; gp++) {
            const uint32_t soff = (uint32_t)(OFF_ST + (gp>>2)*4096 + (t>>3)*256
                                             + (t&7)*32 + (gp&3)*8);
            const float2 h2 = *reinterpret_cast<const float2*>(smem + soff);
            v0 = fmaf(sWo[      gp*2], h2.x, fmaf(sWo[      gp*2+1], h2.y, v0));
            v1 = fmaf(sWo[ 64 + gp*2], h2.x, fmaf(sWo[ 64 + gp*2+1], h2.y, v1));
            v2 = fmaf(sWo[128 + gp*2], h2.x, fmaf(sWo[128 + gp*2+1], h2.y, v2));
        }
        const int p = blockIdx.x * TPB + t;
        const int b = (p >= N) ? 1 : 0;
        const int n = p - b * N;
        out[(b*3 + 0) * N + n] = tanhf(v0 + __ldg(&b_out[0])) * 10.0f;
        out[(b*3 + 1) * N + n] = tanhf(v1 + __ldg(&b_out[1])) * 10.0f;
        out[(b*3 + 2) * N + n] = tanhf(v2 + __ldg(&b_out[2])) * 10.0f;
    }
}

extern "C" void kernel_launch(void* const* d_in, const int* in_sizes, int n_in,
                              void* d_out, int out_size) {
    const float* coords = (const float*)d_in[0];
    const float* W_h    = (const float*)d_in[1];
    const float* U_h    = (const float*)d_in[2];
    const float* b_h    = (const float*)d_in[3];
    const float* W_tau  = (const float*)d_in[4];
    const float* U_tau  = (const float*)d_in[5];
    const float* b_tau  = (const float*)d_in[6];
    const float* W_out  = (const float*)d_in[7];
    const float* b_out  = (const float*)d_in[8];
    float* out = (float*)d_out;

    const int npts = in_sizes[0] / 3;   // B*N = 221184, divisible by 128
    const int N    = npts / 2;

    cudaFuncSetAttribute(liquid_ode_mma_kernel,
                         cudaFuncAttributeMaxDynamicSharedMemorySize,
                         SMEM_BYTES);

    const int grid = npts / TPB;
    liquid_ode_mma_kernel<<<grid, TPB, SMEM_BYTES>>>(coords,
                                                     W_h, U_h, b_h,
                                                     W_tau, U_tau, b_tau,
                                                     W_out, b_out,
                                                     out, N);
}

// round 14
// speedup vs baseline: 1.1733x; 1.1733x over previous
#include <cuda_runtime.h>
#include <cuda_fp16.h>
#include <cstdint>
#include <cmath>

#define TPB    128
#define HD     64
#define STEPS  8

// SW128 swizzle (Swizzle<3,4,3>): XOR bits[6:4] with bits[9:7]
#define SWZ(o) ((o) ^ (((o) >> 3) & 0x70u))

// ---------------- SMEM layout (bytes) ----------------
#define OFF_WT    0        // W_tau fp16 [64 n][64 k] swz (128B rows)  = 8192
#define OFF_WH    8192     // W_h                                        8192
#define OFF_UBT   16384    // U_tau|b_tau fp16 [64 n][16 k] (32B rows) = 2048
#define OFF_UBH   18432    // U_h|b_h                                    2048
#define OFF_WO    20480    // W_out 3x64 f32 = 768, pad 1024
#define OFF_COORD 21504    // 128 x float4                               2048
#define OFF_ST    23552    // state fp32 float2 x 4096 slots           = 32768
#define OFF_LUT   56320    // G lut: 512 x float2 {g, dg}              = 4096
#define SMEM_BYTES 60416   // x3 blocks = 181 KB < 228 KB/SM

__device__ __forceinline__ uint32_t smem_u32(const void* p) {
    uint32_t a;
    asm("{ .reg .u64 tmp; cvta.to.shared.u64 tmp, %1; cvt.u32.u64 %0, tmp; }"
        : "=r"(a) : "l"(p));
    return a;
}

// fp16 mma.sync (sm_80 baseline ISA, legal on compute_103)
#define MMA(D, A, B0, B1)                                                        \
    asm volatile("mma.sync.aligned.m16n8k16.row.col.f32.f16.f16.f32 "            \
        "{%0,%1,%2,%3}, {%4,%5,%6,%7}, {%8,%9}, {%0,%1,%2,%3};"                  \
        : "+f"((D)[0]), "+f"((D)[1]), "+f"((D)[2]), "+f"((D)[3])                 \
        : "r"((A)[0]), "r"((A)[1]), "r"((A)[2]), "r"((A)[3]),                    \
          "r"(B0), "r"(B1))

#define LDSM_X4(R, addr)                                                         \
    asm volatile("ldmatrix.sync.aligned.m8n8.x4.shared.b16 {%0,%1,%2,%3}, [%4];" \
        : "=r"((R)[0]), "=r"((R)[1]), "=r"((R)[2]), "=r"((R)[3])                 \
        : "r"(addr))

#define LDSM_X2(R, addr)                                                         \
    asm volatile("ldmatrix.sync.aligned.m8n8.x2.shared.b16 {%0,%1}, [%2];"       \
        : "=r"((R)[0]), "=r"((R)[1]) : "r"(addr))

#define TANHF(r, x) asm("tanh.approx.f32 %0, %1;" : "=f"(r) : "f"(x))

// epilogue for one (row, col-pair). State slot: fp32 float2, lane-private.
// tau path via LUT: G(ta) = 0.125/tau, nodes at step 1/32 over [-8,8].
// h' = h + 0.125*(sigmoid(fa) - h/tau) = fmaf(-h, G, fmaf(0.0625, th, h+0.0625))
// with th = tanh(fa/2).
__device__ __forceinline__ uint32_t epi2(
    float ta0, float ta1, float fa0, float fa1,
    char* smem, uint32_t soff, const float2* lut)
{
    const float2 hold = *reinterpret_cast<const float2*>(smem + soff);

    float xi0 = fminf(fmaxf(fmaf(ta0, 32.0f, 256.0f), 0.0f), 511.0f);
    float xi1 = fminf(fmaxf(fmaf(ta1, 32.0f, 256.0f), 0.0f), 511.0f);
    const int i0 = (int)xi0;
    const int i1 = (int)xi1;
    const float2 e0 = lut[i0];
    const float2 e1 = lut[i1];
    const float g0 = fmaf(xi0 - (float)i0, e0.y, e0.x);
    const float g1 = fmaf(xi1 - (float)i1, e1.y, e1.x);

    float th0, th1;
    TANHF(th0, 0.5f * fa0);
    TANHF(th1, 0.5f * fa1);

    const float h0n = fmaf(-hold.x, g0, fmaf(0.0625f, th0, hold.x + 0.0625f));
    const float h1n = fmaf(-hold.y, g1, fmaf(0.0625f, th1, hold.y + 0.0625f));

    *reinterpret_cast<float2*>(smem + soff) = make_float2(h0n, h1n);
    __half2 hp = __floats2half2_rn(h0n, h1n);
    return *reinterpret_cast<uint32_t*>(&hp);
}

// one recurrence step: MMAs read acur, epilogues write anx (+ state SMEM).
// p2=1 B address = boff ^ 64 (pre-swizzle bit 6 clear -> XOR exact; verified R13)
__device__ __forceinline__ void do_step(
    char* smem,
    const uint32_t (&acur)[2][4][4], uint32_t (&anx)[2][4][4],
    const uint32_t (&acoord)[2][4],
    const uint32_t (&boffT)[8],
    uint32_t ubbT, uint32_t stb, const float2* lut)
{
    #pragma unroll
    for (int nt = 0; nt < 8; nt++) {
        float dt0[4] = {0,0,0,0}, dt1[4] = {0,0,0,0};
        float df0[4] = {0,0,0,0}, df1[4] = {0,0,0,0};

        #pragma unroll
        for (int p2 = 0; p2 < 2; p2++) {
            const uint32_t ba = p2 ? (boffT[nt] ^ 64u) : boffT[nt];
            uint32_t bt[4], bh[4];
            LDSM_X4(bt, ba);
            LDSM_X4(bh, ba + 8192u);   // W_h mirrors W_tau layout (bank offset)
            #pragma unroll
            for (int q = 0; q < 2; q++) {
                const int kk = 2*p2 + q;
                MMA(dt0, acur[0][kk], bt[2*q], bt[2*q+1]);
                MMA(dt1, acur[1][kk], bt[2*q], bt[2*q+1]);
                MMA(df0, acur[0][kk], bh[2*q], bh[2*q+1]);
                MMA(df1, acur[1][kk], bh[2*q], bh[2*q+1]);
            }
        }
        // augmented-K chunk: A = (cx,cy,cz,1,0...), B = (U|b|0...) rows
        {
            uint32_t ubt[2], ubh[2];
            LDSM_X2(ubt, ubbT + (uint32_t)(nt*256));
            LDSM_X2(ubh, ubbT + (uint32_t)(nt*256) + 2048u);
            MMA(dt0, acoord[0], ubt[0], ubt[1]);
            MMA(dt1, acoord[1], ubt[0], ubt[1]);
            MMA(df0, acoord[0], ubh[0], ubh[1]);
            MMA(df1, acoord[1], ubh[0], ubh[1]);
        }

        // epilogues: lane-private fp32 state; outputs ARE next A fragments
        const uint32_t sbase = stb + (uint32_t)(nt*4096);
        anx[0][nt>>1][(nt&1)*2 + 0] = epi2(dt0[0], dt0[1], df0[0], df0[1], smem, sbase + 0,   lut);
        anx[0][nt>>1][(nt&1)*2 + 1] = epi2(dt0[2], dt0[3], df0[2], df0[3], smem, sbase + 256, lut);
        anx[1][nt>>1][(nt&1)*2 + 0] = epi2(dt1[0], dt1[1], df1[0], df1[1], smem, sbase + 512, lut);
        anx[1][nt>>1][(nt&1)*2 + 1] = epi2(dt1[2], dt1[3], df1[2], df1[3], smem, sbase + 768, lut);
    }
}

__global__ void __launch_bounds__(TPB, 3) liquid_ode_mma_kernel(
    const float* __restrict__ coords,
    const float* __restrict__ W_h,
    const float* __restrict__ U_h,
    const float* __restrict__ b_h,
    const float* __restrict__ W_tau,
    const float* __restrict__ U_tau,
    const float* __restrict__ b_tau,
    const float* __restrict__ W_out,
    const float* __restrict__ b_out,
    float* __restrict__ out,
    int N)
{
    extern __shared__ char smem[];
    const uint32_t sb = smem_u32(smem);
    const int t    = threadIdx.x;
    const int lane = t & 31;
    const int wid  = t >> 5;
    const int gq   = lane >> 2;
    const int tig  = lane & 3;
    const int warpM = wid * 32;

    // ---- prologue ----
    for (int idx = t; idx < HD * HD; idx += TPB) {
        const int n = idx >> 6, k = idx & 63;
        const uint32_t sw = SWZ((uint32_t)(n * 128 + k * 2));
        *reinterpret_cast<__half*>(smem + OFF_WT + sw) = __float2half_rn(W_tau[idx]);
        *reinterpret_cast<__half*>(smem + OFF_WH + sw) = __float2half_rn(W_h[idx]);
    }
    for (int idx = t; idx < HD * 16; idx += TPB) {
        const int n = idx >> 4, k = idx & 15;
        float vt = 0.f, vh = 0.f;
        if (k < 3)       { vt = U_tau[n*3 + k]; vh = U_h[n*3 + k]; }
        else if (k == 3) { vt = b_tau[n];       vh = b_h[n]; }
        *reinterpret_cast<__half*>(smem + OFF_UBT + idx*2) = __float2half_rn(vt);
        *reinterpret_cast<__half*>(smem + OFF_UBH + idx*2) = __float2half_rn(vh);
    }
    // G lut: nodes x_i = -8 + i/32, entry = {G(x_i), G(x_{i+1}) - G(x_i)}
    {
        float2* lutw = reinterpret_cast<float2*>(smem + OFF_LUT);
        for (int i = t; i < 512; i += TPB) {
            const float x0 = -8.0f + (float)i * (1.0f/32.0f);
            const float ga = 0.125f / fmaf(9.9f, log1pf(expf(x0)), 0.1f);
            const float gb = 0.125f / fmaf(9.9f, log1pf(expf(x0 + (1.0f/32.0f))), 0.1f);
            lutw[i] = make_float2(ga, gb - ga);
        }
    }
    {
        const int p = blockIdx.x * TPB + t;
        reinterpret_cast<float4*>(smem + OFF_COORD)[t] =
            make_float4(coords[3*p], coords[3*p+1], coords[3*p+2], 0.f);
        float* sWo = reinterpret_cast<float*>(smem + OFF_WO);
        for (int i = t; i < 192; i += TPB) sWo[i] = W_out[i];
        float2* s2 = reinterpret_cast<float2*>(smem + OFF_ST);
        for (int i = t; i < 4096; i += TPB) s2[i] = make_float2(0.f, 0.f);   // h = 0
    }
    __syncthreads();

    const float2* lut = reinterpret_cast<const float2*>(smem + OFF_LUT);

    // constant A-fragment regs for the augmented-K chunk: cols (cx,cy,cz,1,0..)
    uint32_t acoord[2][4];
    {
        const float4* sc = reinterpret_cast<const float4*>(smem + OFF_COORD);
        #pragma unroll
        for (int m = 0; m < 2; m++) {
            const float4 c0 = sc[warpM + m*16 + gq];
            const float4 c1 = sc[warpM + m*16 + gq + 8];
            uint32_t p0 = 0u, p1 = 0u;
            if (tig == 0) {
                __half2 h0 = __floats2half2_rn(c0.x, c0.y);
                __half2 h1 = __floats2half2_rn(c1.x, c1.y);
                p0 = *reinterpret_cast<uint32_t*>(&h0);
                p1 = *reinterpret_cast<uint32_t*>(&h1);
            } else if (tig == 1) {
                __half2 h0 = __floats2half2_rn(c0.z, 1.0f);
                __half2 h1 = __floats2half2_rn(c1.z, 1.0f);
                p0 = *reinterpret_cast<uint32_t*>(&h0);
                p1 = *reinterpret_cast<uint32_t*>(&h1);
            }
            acoord[m][0] = p0;
            acoord[m][1] = p1;
            acoord[m][2] = 0u;
            acoord[m][3] = 0u;
        }
    }

    // precomputed ldmatrix base addresses (p2=0; p2=1 via ^64, SWZ-exact)
    uint32_t boffT[8];
    {
        const uint32_t brow = (uint32_t)(lane & 7);
        const uint32_t bcol = ((lane & 16) ? 32u : 0u) + ((lane & 8) ? 16u : 0u);
        #pragma unroll
        for (int nt = 0; nt < 8; nt++)
            boffT[nt] = sb + OFF_WT +
                SWZ((uint32_t)((nt*8 + brow) * 128) + bcol);
    }
    const uint32_t ubbT = sb + OFF_UBT + (uint32_t)((lane & 7) * 32)
                        + ((lane & 8) ? 16u : 0u);
    const uint32_t stb  = (uint32_t)(OFF_ST + wid*1024 + lane*8);

    // A double buffer (h fp16), register-resident; h0 = 0
    uint32_t a0[2][4][4], a1[2][4][4];
    #pragma unroll
    for (int m = 0; m < 2; m++)
        #pragma unroll
        for (int kk = 0; kk < 4; kk++)
            #pragma unroll
            for (int j = 0; j < 4; j++) { a0[m][kk][j] = 0u; a1[m][kk][j] = 0u; }

    // ---- 8 steps, sync-free, ping-pong A buffers (no copy) ----
    #pragma unroll 1
    for (int s = 0; s < STEPS / 2; s++) {
        do_step(smem, a0, a1, acoord, boffT, ubbT, stb, lut);
        do_step(smem, a1, a0, acoord, boffT, ubbT, stb, lut);
    }

    __syncwarp();   // state rows are warp-private; cross-lane writes -> readout

    // ---- readout: thread t reads its own row t from fp32 state ----
    {
        const float* sWo = reinterpret_cast<const float*>(smem + OFF_WO);
        float v0 = 0.f, v1 = 0.f, v2 = 0.f;
        #pragma unroll
        for (int gp = 0; gp < 32; gp++) {
            const uint32_t soff = (uint32_t)(OFF_ST + (gp>>2)*4096 + (t>>3)*256
                                             + (t&7)*32 + (gp&3)*8);
            const float2 h2 = *reinterpret_cast<const float2*>(smem + soff);
            v0 = fmaf(sWo[      gp*2], h2.x, fmaf(sWo[      gp*2+1], h2.y, v0));
            v1 = fmaf(sWo[ 64 + gp*2], h2.x, fmaf(sWo[ 64 + gp*2+1], h2.y, v1));
            v2 = fmaf(sWo[128 + gp*2], h2.x, fmaf(sWo[128 + gp*2+1], h2.y, v2));
        }
        const int p = blockIdx.x * TPB + t;
        const int b = (p >= N) ? 1 : 0;
        const int n = p - b * N;
        out[(b*3 + 0) * N + n] = tanhf(v0 + __ldg(&b_out[0])) * 10.0f;
        out[(b*3 + 1) * N + n] = tanhf(v1 + __ldg(&b_out[1])) * 10.0f;
        out[(b*3 + 2) * N + n] = tanhf(v2 + __ldg(&b_out[2])) * 10.0f;
    }
}

extern "C" void kernel_launch(void* const* d_in, const int* in_sizes, int n_in,
                              void* d_out, int out_size) {
    const float* coords = (const float*)d_in[0];
    const float* W_h    = (const float*)d_in[1];
    const float* U_h    = (const float*)d_in[2];
    const float* b_h    = (const float*)d_in[3];
    const float* W_tau  = (const float*)d_in[4];
    const float* U_tau  = (const float*)d_in[5];
    const float* b_tau  = (const float*)d_in[6];
    const float* W_out  = (const float*)d_in[7];
    const float* b_out  = (const float*)d_in[8];
    float* out = (float*)d_out;

    const int npts = in_sizes[0] / 3;   // B*N = 221184, divisible by 128
    const int N    = npts / 2;

    cudaFuncSetAttribute(liquid_ode_mma_kernel,
                         cudaFuncAttributeMaxDynamicSharedMemorySize,
                         SMEM_BYTES);

    const int grid = npts / TPB;
    liquid_ode_mma_kernel<<<grid, TPB, SMEM_BYTES>>>(coords,
                                                     W_h, U_h, b_h,
                                                     W_tau, U_tau, b_tau,
                                                     W_out, b_out,
                                                     out, N);
}